// round 13
// baseline (speedup 1.0000x reference)
#include <cuda_runtime.h>
#include <cuda_bf16.h>

// EMA scan y[n] = w*x[n] + (1-w)*y[n-1] over the contiguous frames axis (2048).
// input (16,8,256,2048) f32; initial_state (16,8,256); weight (8,256) clamped.
//
// Structure (best-known, R12): warp-autonomous, one warp per channel, 8 warps
// per CTA (grid 4096). 16 rounds of 128 frames; in round k lane l owns float4
// 32k+l -> perfectly coalesced LDG.128/STG.128. Per 4-frame segment the
// recurrence is the affine map y -> r*y + b with identical r = (1-w)^4 across
// lanes, so only the offset b is Kogge-Stone scanned (5 shuffles, multipliers
// r^d). 8-deep register ring keeps ~8 loads in flight per warp.
//
// R13 (single-variable): stores use DEFAULT st.global (write-back, normal
// eviction age -> longer DRAM write bursts) instead of .cs evict-first;
// loads keep ld.global.cs.L2::256B (best measured).

#define NFRAMES   2048
#define NCHANNELS (16 * 8 * 256)
#define WARPS_PER_CTA 8
#define NROUNDS   16
#define RING      8

__device__ __forceinline__ float4 ldcs4(const float4* p) {
    float4 v;
    asm volatile("ld.global.cs.L2::256B.v4.f32 {%0,%1,%2,%3}, [%4];"
                 : "=f"(v.x), "=f"(v.y), "=f"(v.z), "=f"(v.w) : "l"(p));
    return v;
}
__device__ __forceinline__ void stg4(float4* p, float4 v) {
    asm volatile("st.global.v4.f32 [%0], {%1,%2,%3,%4};"
                 :: "l"(p), "f"(v.x), "f"(v.y), "f"(v.z), "f"(v.w) : "memory");
}

__global__ __launch_bounds__(32 * WARPS_PER_CTA, 4)
void ema_scan_kernel(const float* __restrict__ in,
                     const float* __restrict__ init_state,
                     const float* __restrict__ wt,
                     float* __restrict__ out)
{
    const int lane = threadIdx.x & 31;
    const int warp = threadIdx.x >> 5;
    const int ch   = blockIdx.x * WARPS_PER_CTA + warp;

    float w = wt[ch & 2047];
    w = fminf(fmaxf(w, 0.0f), 1.0f);
    const float omw = 1.0f - w;

    const float4* ip = reinterpret_cast<const float4*>(in + (size_t)ch * NFRAMES);
    float4*       op = reinterpret_cast<float4*>(out + (size_t)ch * NFRAMES);

    // Prime the ring: first 8 rounds' data in flight
    float4 xs[RING];
    #pragma unroll
    for (int k = 0; k < RING; ++k)
        xs[k] = ldcs4(ip + k * 32 + lane);

    // Powers of r = (1-w)^4
    float r1 = omw * omw; r1 = r1 * r1;
    const float r2  = r1 * r1;
    const float r4  = r2 * r2;
    const float r8  = r4 * r4;
    const float r16 = r8 * r8;

    // r^(lane+1) for the exit-state FMA
    float rl = r1;
    if (lane & 1)  rl *= r1;
    if (lane & 2)  rl *= r2;
    if (lane & 4)  rl *= r4;
    if (lane & 8)  rl *= r8;
    if (lane & 16) rl *= r16;
    const float rlr = rl;

    float ycarry = init_state[ch];

    #pragma unroll
    for (int k = 0; k < NROUNDS; ++k) {
        const float4 x = xs[k % RING];
        // Refill this slot with round k+8 (keeps ~8 loads in flight)
        if (k + RING < NROUNDS)
            xs[k % RING] = ldcs4(ip + (k + RING) * 32 + lane);

        // Segment offset: 4-frame local recurrence from zero state
        float b = w * x.x;
        b = omw * b + w * x.y;
        b = omw * b + w * x.z;
        b = omw * b + w * x.w;

        // Inclusive Kogge-Stone scan of b; active lanes' multiplier is r^d
        float p;
        p = __shfl_up_sync(0xffffffffu, b, 1);  if (lane >= 1)  b = r1  * p + b;
        p = __shfl_up_sync(0xffffffffu, b, 2);  if (lane >= 2)  b = r2  * p + b;
        p = __shfl_up_sync(0xffffffffu, b, 4);  if (lane >= 4)  b = r4  * p + b;
        p = __shfl_up_sync(0xffffffffu, b, 8);  if (lane >= 8)  b = r8  * p + b;
        p = __shfl_up_sync(0xffffffffu, b, 16); if (lane >= 16) b = r16 * p + b;

        // Exit state of this lane's segment; entering state; round carry
        const float yexit  = rlr * ycarry + b;
        float yenter = __shfl_up_sync(0xffffffffu, yexit, 1);
        if (lane == 0) yenter = ycarry;
        ycarry = __shfl_sync(0xffffffffu, yexit, 31);

        // Replay exactly as the reference recurrence
        float y = yenter;
        float4 o;
        y = w * x.x + omw * y; o.x = y;
        y = w * x.y + omw * y; o.y = y;
        y = w * x.z + omw * y; o.z = y;
        y = w * x.w + omw * y; o.w = y;

        stg4(op + k * 32 + lane, o);
    }
}

extern "C" void kernel_launch(void* const* d_in, const int* in_sizes, int n_in,
                              void* d_out, int out_size)
{
    const float* input   = (const float*)d_in[0];
    const float* init_st = (const float*)d_in[1];
    const float* weight  = (const float*)d_in[2];
    float* out = (float*)d_out;

    ema_scan_kernel<<<NCHANNELS / WARPS_PER_CTA, 32 * WARPS_PER_CTA>>>(
        input, init_st, weight, out);
}

// round 16
// speedup vs baseline: 1.0194x; 1.0194x over previous
#include <cuda_runtime.h>
#include <cuda_bf16.h>

// EMA scan y[n] = w*x[n] + (1-w)*y[n-1] over the contiguous frames axis (2048).
// input (16,8,256,2048) f32; initial_state (16,8,256); weight (8,256) clamped.
//
// FINAL (R12 configuration — best measured: 82.0us wall, DRAM 81.3%):
// - Warp-autonomous: one warp per channel, 8 warps/CTA (grid 4096), no smem,
//   no __syncthreads. 16 rounds of 128 frames; in round k lane l owns float4
//   32k+l -> perfectly coalesced LDG.128/STG.128.
// - Per 4-frame segment the recurrence is the affine map y -> r*y + b with
//   identical r = (1-w)^4 across lanes (w is per-channel), so only the offset
//   b is Kogge-Stone scanned (5 shuffles, multipliers r^d from a squaring
//   chain). Carry across rounds via lane-31 broadcast.
// - 8-deep register ring keeps ~8 loads in flight per warp (64 regs, occ 43%).
// - ld.global.cs.L2::256B loads + st.global.cs stores (measured best: evict-
//   first keeps the 537MB stream from thrashing L2; default stores cost ~1%,
//   confirmed by R13's controlled test).
//
// Session evidence: DRAM plateaus at ~6.44 TB/s across occ 26-43%, hint
// variants, and CTA shapes, with all other pipes <45% — this is the practical
// 50/50 R+W HBM ceiling; bytes are algorithmically minimal.
// (R14 resubmission: previous run hit a container infra failure.)

#define NFRAMES   2048
#define NCHANNELS (16 * 8 * 256)
#define WARPS_PER_CTA 8
#define NROUNDS   16
#define RING      8

__device__ __forceinline__ float4 ldcs4(const float4* p) {
    float4 v;
    asm volatile("ld.global.cs.L2::256B.v4.f32 {%0,%1,%2,%3}, [%4];"
                 : "=f"(v.x), "=f"(v.y), "=f"(v.z), "=f"(v.w) : "l"(p));
    return v;
}
__device__ __forceinline__ void stcs4(float4* p, float4 v) {
    asm volatile("st.global.cs.v4.f32 [%0], {%1,%2,%3,%4};"
                 :: "l"(p), "f"(v.x), "f"(v.y), "f"(v.z), "f"(v.w) : "memory");
}

__global__ __launch_bounds__(32 * WARPS_PER_CTA, 4)
void ema_scan_kernel(const float* __restrict__ in,
                     const float* __restrict__ init_state,
                     const float* __restrict__ wt,
                     float* __restrict__ out)
{
    const int lane = threadIdx.x & 31;
    const int warp = threadIdx.x >> 5;
    const int ch   = blockIdx.x * WARPS_PER_CTA + warp;

    float w = wt[ch & 2047];
    w = fminf(fmaxf(w, 0.0f), 1.0f);
    const float omw = 1.0f - w;

    const float4* ip = reinterpret_cast<const float4*>(in + (size_t)ch * NFRAMES);
    float4*       op = reinterpret_cast<float4*>(out + (size_t)ch * NFRAMES);

    // Prime the ring: first 8 rounds' data in flight
    float4 xs[RING];
    #pragma unroll
    for (int k = 0; k < RING; ++k)
        xs[k] = ldcs4(ip + k * 32 + lane);

    // Powers of r = (1-w)^4
    float r1 = omw * omw; r1 = r1 * r1;
    const float r2  = r1 * r1;
    const float r4  = r2 * r2;
    const float r8  = r4 * r4;
    const float r16 = r8 * r8;

    // r^(lane+1) for the exit-state FMA
    float rl = r1;
    if (lane & 1)  rl *= r1;
    if (lane & 2)  rl *= r2;
    if (lane & 4)  rl *= r4;
    if (lane & 8)  rl *= r8;
    if (lane & 16) rl *= r16;
    const float rlr = rl;

    float ycarry = init_state[ch];

    #pragma unroll
    for (int k = 0; k < NROUNDS; ++k) {
        const float4 x = xs[k % RING];
        // Refill this slot with round k+8 (keeps ~8 loads in flight)
        if (k + RING < NROUNDS)
            xs[k % RING] = ldcs4(ip + (k + RING) * 32 + lane);

        // Segment offset: 4-frame local recurrence from zero state
        float b = w * x.x;
        b = omw * b + w * x.y;
        b = omw * b + w * x.z;
        b = omw * b + w * x.w;

        // Inclusive Kogge-Stone scan of b; active lanes' multiplier is r^d
        float p;
        p = __shfl_up_sync(0xffffffffu, b, 1);  if (lane >= 1)  b = r1  * p + b;
        p = __shfl_up_sync(0xffffffffu, b, 2);  if (lane >= 2)  b = r2  * p + b;
        p = __shfl_up_sync(0xffffffffu, b, 4);  if (lane >= 4)  b = r4  * p + b;
        p = __shfl_up_sync(0xffffffffu, b, 8);  if (lane >= 8)  b = r8  * p + b;
        p = __shfl_up_sync(0xffffffffu, b, 16); if (lane >= 16) b = r16 * p + b;

        // Exit state of this lane's segment; entering state; round carry
        const float yexit  = rlr * ycarry + b;
        float yenter = __shfl_up_sync(0xffffffffu, yexit, 1);
        if (lane == 0) yenter = ycarry;
        ycarry = __shfl_sync(0xffffffffu, yexit, 31);

        // Replay exactly as the reference recurrence
        float y = yenter;
        float4 o;
        y = w * x.x + omw * y; o.x = y;
        y = w * x.y + omw * y; o.y = y;
        y = w * x.z + omw * y; o.z = y;
        y = w * x.w + omw * y; o.w = y;

        stcs4(op + k * 32 + lane, o);
    }
}

extern "C" void kernel_launch(void* const* d_in, const int* in_sizes, int n_in,
                              void* d_out, int out_size)
{
    const float* input   = (const float*)d_in[0];
    const float* init_st = (const float*)d_in[1];
    const float* weight  = (const float*)d_in[2];
    float* out = (float*)d_out;

    ema_scan_kernel<<<NCHANNELS / WARPS_PER_CTA, 32 * WARPS_PER_CTA>>>(
        input, init_st, weight, out);
}